// round 3
// baseline (speedup 1.0000x reference)
#include <cuda_runtime.h>
#include <cuda_bf16.h>
#include <stdint.h>
#include <math_constants.h>

#define B_  256
#define C_  345
#define D_  512
#define N_  50000
#define KN  5
#define BM  128
#define BN  128
#define BK  32
#define NTILES 391             /* ceil(50000 / 128) */

/* ---------------- device scratch (static allocation only) ---------------- */
__device__ __align__(16) float          g_p[B_ * C_];        // softmax_out
__device__ float                        g_rowsq[B_];         // ||p_b||^2
__device__ __align__(16) float          g_fn[B_ * D_];       // f_norm fp32
__device__ __align__(16) __nv_bfloat16  g_fnb[B_ * D_];      // f_norm bf16 (GEMM A)
__device__ int                          g_owner[N_];         // scatter owner LUT
__device__ __align__(16) float          g_cv[(size_t)B_ * NTILES * 6];  // cand values
__device__ __align__(16) int            g_ci[(size_t)B_ * NTILES * 6];  // cand indices
__device__ int                          g_idx[B_ * KN];      // idx_near
__device__ float                        g_lossparts[B_];

__device__ __forceinline__ int clampN(int n) {
  return (n < 0) ? 0 : ((n >= N_) ? (N_ - 1) : n);
}

__device__ __forceinline__ bool betterf(float v, int i, float v2, int i2) {
  return (v > v2) || (v == v2 && i < i2);
}

__device__ __forceinline__ void ins6(float v, int id, float* bv, int* bi) {
  if (betterf(v, id, bv[5], bi[5])) {
    bv[5] = v; bi[5] = id;
#pragma unroll
    for (int j = 5; j > 0; j--) {
      if (betterf(bv[j], bi[j], bv[j - 1], bi[j - 1])) {
        float tv = bv[j]; bv[j] = bv[j - 1]; bv[j - 1] = tv;
        int  ti = bi[j]; bi[j] = bi[j - 1]; bi[j - 1] = ti;
      }
    }
  }
}

/* ---------------- tiny prep kernels ---------------- */
__global__ void init_owner_k() {
  int i = blockIdx.x * blockDim.x + threadIdx.x;
  if (i < N_) g_owner[i] = -1;
}

__global__ void scatter_owner_k(const int* __restrict__ trg) {
  int b = threadIdx.x;
  atomicMax(&g_owner[clampN(trg[b])], b);   // last-write-wins (max batch idx)
}

/* softmax (blocks 0..255) + fnorm (blocks 256..511) fused */
__global__ void prep_k(const float* __restrict__ pred, const float* __restrict__ feat) {
  int t = threadIdx.x;
  __shared__ float red[128];
  if (blockIdx.x < B_) {
    int b = blockIdx.x;
    const float* row = pred + (size_t)b * C_;
    float mx = -CUDART_INF_F;
    for (int c = t; c < C_; c += 128) mx = fmaxf(mx, row[c]);
    red[t] = mx; __syncthreads();
    for (int s = 64; s > 0; s >>= 1) { if (t < s) red[t] = fmaxf(red[t], red[t + s]); __syncthreads(); }
    mx = red[0]; __syncthreads();
    float sm = 0.f;
    for (int c = t; c < C_; c += 128) sm += expf(row[c] - mx);
    red[t] = sm; __syncthreads();
    for (int s = 64; s > 0; s >>= 1) { if (t < s) red[t] += red[t + s]; __syncthreads(); }
    float inv = 1.f / red[0]; __syncthreads();
    float sq = 0.f;
    for (int c = t; c < C_; c += 128) {
      float v = expf(row[c] - mx) * inv;
      g_p[(size_t)b * C_ + c] = v;
      sq += v * v;
    }
    red[t] = sq; __syncthreads();
    for (int s = 64; s > 0; s >>= 1) { if (t < s) red[t] += red[t + s]; __syncthreads(); }
    if (t == 0) g_rowsq[b] = red[0];
  } else {
    int b = blockIdx.x - B_;
    const float* row = feat + (size_t)b * D_;
    float sq = 0.f;
    for (int c = t; c < D_; c += 128) { float v = row[c]; sq += v * v; }
    red[t] = sq; __syncthreads();
    for (int s = 64; s > 0; s >>= 1) { if (t < s) red[t] += red[t + s]; __syncthreads(); }
    float inv = 1.f / fmaxf(sqrtf(red[0]), 1e-12f);
    for (int c = t; c < D_; c += 128) {
      float v = row[c] * inv;
      g_fn[(size_t)b * D_ + c]  = v;
      g_fnb[(size_t)b * D_ + c] = __float2bfloat16(v);
    }
  }
}

/* ---- bf16 mma.sync GEMM + fused per-tile top-6: cand = topk(f_norm @ bank'^T) ---- */
/* bank' rows with owner>=0 are read from g_fn (inline scatter).                      */
__global__ void __launch_bounds__(256) gemm_k(const float* __restrict__ fb) {
  /* smem reuse: [phase A] sA(20480) + sB(20480) double-buffered GEMM tiles
     [phase B] scanTile 64x132 f32 (33792) + merge bufs (6144+6144) = 46080 */
  __shared__ __align__(16) char smemRaw[46080];
  __shared__ const float* sPtr[128];

  typedef __nv_bfloat16 (*TileT)[BM][40];
  TileT sA = reinterpret_cast<TileT>(smemRaw);            // [2][128][40]
  TileT sB = reinterpret_cast<TileT>(smemRaw + 20480);    // [2][128][40]

  const int tid  = threadIdx.x;
  const int lane = tid & 31;
  const int warp = tid >> 5;
  const int wm   = warp >> 2;      // 0..1  (64 rows each)
  const int wn   = warp & 3;       // 0..3  (32 cols each)
  const int mBase = blockIdx.y * BM;
  const int nBase = blockIdx.x * BN;

  /* per-tile source pointers with inline scatter */
  if (tid < 128) {
    int g = nBase + tid;
    if (g >= N_) g = N_ - 1;
    int ow = g_owner[g];
    sPtr[tid] = (ow >= 0) ? (g_fn + (size_t)ow * D_) : (fb + (size_t)g * D_);
  }
  __syncthreads();

  float acc[4][4][4];
#pragma unroll
  for (int i = 0; i < 4; i++)
#pragma unroll
    for (int j = 0; j < 4; j++)
#pragma unroll
      for (int k = 0; k < 4; k++) acc[i][j][k] = 0.f;

  uint4  aS[2];
  float4 bS[4];

  /* ---- stage 0 global load ---- */
  {
#pragma unroll
    for (int t = 0; t < 2; t++) {
      int idx = tid + t * 256, m = idx >> 2, kc = idx & 3;
      aS[t] = *(const uint4*)(g_fnb + (size_t)(mBase + m) * D_ + kc * 8);
    }
#pragma unroll
    for (int t = 0; t < 4; t++) {
      int idx = tid + t * 256, n = idx >> 3, kc = idx & 7;
      bS[t] = *(const float4*)(sPtr[n] + kc * 4);
    }
  }
#pragma unroll
  for (int t = 0; t < 2; t++) {
    int idx = tid + t * 256, m = idx >> 2, kc = idx & 3;
    *(uint4*)&sA[0][m][kc * 8] = aS[t];
  }
#pragma unroll
  for (int t = 0; t < 4; t++) {
    int idx = tid + t * 256, n = idx >> 3, kc = idx & 7;
    __nv_bfloat162 lo = __floats2bfloat162_rn(bS[t].x, bS[t].y);
    __nv_bfloat162 hi = __floats2bfloat162_rn(bS[t].z, bS[t].w);
    uint2 v; v.x = *(uint32_t*)&lo; v.y = *(uint32_t*)&hi;
    *(uint2*)&sB[0][n][kc * 4] = v;
  }
  __syncthreads();

#pragma unroll 1
  for (int kt = 0; kt < 16; kt++) {
    const int buf = kt & 1;
    if (kt + 1 < 16) {
      const int k0 = (kt + 1) * BK;
#pragma unroll
      for (int t = 0; t < 2; t++) {
        int idx = tid + t * 256, m = idx >> 2, kc = idx & 3;
        aS[t] = *(const uint4*)(g_fnb + (size_t)(mBase + m) * D_ + k0 + kc * 8);
      }
#pragma unroll
      for (int t = 0; t < 4; t++) {
        int idx = tid + t * 256, n = idx >> 3, kc = idx & 7;
        bS[t] = *(const float4*)(sPtr[n] + k0 + kc * 4);
      }
    }
#pragma unroll
    for (int ks = 0; ks < 2; ks++) {
      const int kk = ks * 16 + (lane & 3) * 2;
      uint32_t af[4][4], bfr[4][2];
#pragma unroll
      for (int mi = 0; mi < 4; mi++) {
        int r = wm * 64 + mi * 16 + (lane >> 2);
        af[mi][0] = *(const uint32_t*)&sA[buf][r][kk];
        af[mi][1] = *(const uint32_t*)&sA[buf][r + 8][kk];
        af[mi][2] = *(const uint32_t*)&sA[buf][r][kk + 8];
        af[mi][3] = *(const uint32_t*)&sA[buf][r + 8][kk + 8];
      }
#pragma unroll
      for (int ni = 0; ni < 4; ni++) {
        int n = wn * 32 + ni * 8 + (lane >> 2);
        bfr[ni][0] = *(const uint32_t*)&sB[buf][n][kk];
        bfr[ni][1] = *(const uint32_t*)&sB[buf][n][kk + 8];
      }
#pragma unroll
      for (int mi = 0; mi < 4; mi++)
#pragma unroll
        for (int ni = 0; ni < 4; ni++)
          asm volatile(
            "mma.sync.aligned.m16n8k16.row.col.f32.bf16.bf16.f32 "
            "{%0,%1,%2,%3}, {%4,%5,%6,%7}, {%8,%9}, {%0,%1,%2,%3};\n"
            : "+f"(acc[mi][ni][0]), "+f"(acc[mi][ni][1]),
              "+f"(acc[mi][ni][2]), "+f"(acc[mi][ni][3])
            : "r"(af[mi][0]), "r"(af[mi][1]), "r"(af[mi][2]), "r"(af[mi][3]),
              "r"(bfr[ni][0]), "r"(bfr[ni][1]));
    }
    if (kt + 1 < 16) {
      const int nb = (kt + 1) & 1;
#pragma unroll
      for (int t = 0; t < 2; t++) {
        int idx = tid + t * 256, m = idx >> 2, kc = idx & 3;
        *(uint4*)&sA[nb][m][kc * 8] = aS[t];
      }
#pragma unroll
      for (int t = 0; t < 4; t++) {
        int idx = tid + t * 256, n = idx >> 3, kc = idx & 7;
        __nv_bfloat162 lo = __floats2bfloat162_rn(bS[t].x, bS[t].y);
        __nv_bfloat162 hi = __floats2bfloat162_rn(bS[t].z, bS[t].w);
        uint2 v; v.x = *(uint32_t*)&lo; v.y = *(uint32_t*)&hi;
        *(uint2*)&sB[nb][n][kc * 4] = v;
      }
      __syncthreads();
    }
  }

  /* ---- fused epilogue: per-row top-6 of this 128-col tile, in two 64-row halves ---- */
  float* scanTile = (float*)smemRaw;            // [64][132]
  float* mbV = (float*)(smemRaw + 33792);       // [64][4][6]
  int*   mbI = (int*)(smemRaw + 39936);         // [64][4][6]

#pragma unroll 1
  for (int half = 0; half < 2; half++) {
    __syncthreads();   // smem (GEMM tiles / previous half) fully consumed
    if (wm == half) {
#pragma unroll
      for (int mi = 0; mi < 4; mi++) {
        int lr = mi * 16 + (lane >> 2);
#pragma unroll
        for (int ni = 0; ni < 4; ni++) {
          int c = wn * 32 + ni * 8 + (lane & 3) * 2;
          *(float2*)&scanTile[lr * 132 + c]       = make_float2(acc[mi][ni][0], acc[mi][ni][1]);
          *(float2*)&scanTile[(lr + 8) * 132 + c] = make_float2(acc[mi][ni][2], acc[mi][ni][3]);
        }
      }
    }
    __syncthreads();
    /* 256 threads: 4 segments of 32 cols per row (64 rows) */
    {
      int lr  = tid >> 2;
      int seg = tid & 3;
      int cs  = seg * 32;
      float bv[6]; int bi[6];
#pragma unroll
      for (int j = 0; j < 6; j++) { bv[j] = -CUDART_INF_F; bi[j] = 0x7fffffff; }
#pragma unroll 4
      for (int i = 0; i < 32; i++) {
        int gcol = nBase + cs + i;
        float v = scanTile[lr * 132 + cs + i];
        if (gcol < N_) ins6(v, gcol, bv, bi);
      }
#pragma unroll
      for (int j = 0; j < 6; j++) {
        mbV[(lr * 4 + seg) * 6 + j] = bv[j];
        mbI[(lr * 4 + seg) * 6 + j] = bi[j];
      }
    }
    __syncthreads();
    if ((tid & 3) == 0) {
      int lr = tid >> 2;
      float bv[6]; int bi[6];
#pragma unroll
      for (int j = 0; j < 6; j++) { bv[j] = -CUDART_INF_F; bi[j] = 0x7fffffff; }
#pragma unroll
      for (int s = 0; s < 4; s++)
#pragma unroll
        for (int j = 0; j < 6; j++)
          ins6(mbV[(lr * 4 + s) * 6 + j], mbI[(lr * 4 + s) * 6 + j], bv, bi);
      int grow = mBase + half * 64 + lr;
      size_t base = ((size_t)grow * NTILES + blockIdx.x) * 6;
#pragma unroll
      for (int j = 0; j < 6; j++) { g_cv[base + j] = bv[j]; g_ci[base + j] = bi[j]; }
    }
  }
}

/* ---------------- merge per-tile candidates -> global top-6, drop rank-0 -------------- */
__global__ void merge_topk_k() {
  const int b = blockIdx.x, t = threadIdx.x;
  __shared__ float sv[256 * 6];
  __shared__ int   si[256 * 6];

  float bv[6]; int bi[6];
#pragma unroll
  for (int j = 0; j < 6; j++) { bv[j] = -CUDART_INF_F; bi[j] = 0x7fffffff; }

  const float* cv = g_cv + (size_t)b * NTILES * 6;
  const int*   ci = g_ci + (size_t)b * NTILES * 6;
  for (int e = t; e < NTILES * 6; e += 256)
    ins6(cv[e], ci[e], bv, bi);

#pragma unroll
  for (int j = 0; j < 6; j++) { sv[t * 6 + j] = bv[j]; si[t * 6 + j] = bi[j]; }
  __syncthreads();

  if (t < 32) {
    float mv[6]; int mi_[6];
#pragma unroll
    for (int j = 0; j < 6; j++) { mv[j] = -CUDART_INF_F; mi_[j] = 0x7fffffff; }
    for (int src = t; src < 256; src += 32)
      for (int j = 0; j < 6; j++)
        ins6(sv[src * 6 + j], si[src * 6 + j], mv, mi_);
#pragma unroll
    for (int j = 0; j < 6; j++) { sv[t * 6 + j] = mv[j]; si[t * 6 + j] = mi_[j]; }
  }
  __syncthreads();

  if (t == 0) {
    float mv[6]; int mi_[6];
#pragma unroll
    for (int j = 0; j < 6; j++) { mv[j] = -CUDART_INF_F; mi_[j] = 0x7fffffff; }
    for (int src = 0; src < 32; src++)
      for (int j = 0; j < 6; j++)
        ins6(sv[src * 6 + j], si[src * 6 + j], mv, mi_);
#pragma unroll
    for (int j = 1; j < 6; j++) g_idx[b * KN + (j - 1)] = mi_[j];   // drop rank-0
  }
}

/* ---------------- KL term per batch row ---------------- */
__global__ void kl_k(const float* __restrict__ sb) {
  const int b = blockIdx.x, t = threadIdx.x;
  __shared__ float red[128];
  float acc = 0.f;
  for (int k = 0; k < KN; k++) {
    int n  = g_idx[b * KN + k];
    int ow = g_owner[n];
    const float* srow = (ow >= 0) ? (g_p + (size_t)ow * C_)
                                  : (sb + (size_t)n * C_);
    for (int c = t; c < C_; c += 128) {
      float s = srow[c];
      acc += s * (logf(s) - g_p[(size_t)b * C_ + c]);
    }
  }
  red[t] = acc; __syncthreads();
  for (int s = 64; s > 0; s >>= 1) { if (t < s) red[t] += red[t + s]; __syncthreads(); }
  if (t == 0) g_lossparts[b] = red[0];
}

/* ---------------- final: loss = mean(kl) + (||q||^2 - sum rowsq)/B (q = colsum p) ----- */
__global__ void final_k(float* __restrict__ out) {
  __shared__ float r1[512], r2[512], r3[512];
  int t = threadIdx.x;
  float a = 0.f, q2 = 0.f, rr = 0.f;
  if (t < B_) { a = g_lossparts[t]; rr = g_rowsq[t]; }
  for (int c = t; c < C_; c += 512) {
    float s = 0.f;
    for (int b = 0; b < B_; b++) s += g_p[(size_t)b * C_ + c];
    q2 += s * s;
  }
  r1[t] = a; r2[t] = q2; r3[t] = rr; __syncthreads();
  for (int s = 256; s > 0; s >>= 1) {
    if (t < s) { r1[t] += r1[t + s]; r2[t] += r2[t + s]; r3[t] += r3[t + s]; }
    __syncthreads();
  }
  if (t == 0) out[0] = r1[0] / (float)B_ + 1.0f * ((r2[0] - r3[0]) / (float)B_);
}

/* ---------------- launch ---------------- */
extern "C" void kernel_launch(void* const* d_in, const int* in_sizes, int n_in,
                              void* d_out, int out_size) {
  (void)in_sizes; (void)n_in; (void)out_size;
  const float* feat = (const float*)d_in[0];
  const float* pred = (const float*)d_in[1];
  const float* fb   = (const float*)d_in[2];
  const float* sb   = (const float*)d_in[3];
  const int*   trg  = (const int*)d_in[4];   /* JAX x64 disabled -> int32 */

  init_owner_k<<<(N_ + 1023) / 1024, 1024>>>();        // launch 0
  scatter_owner_k<<<1, B_>>>(trg);                     // launch 1
  prep_k<<<2 * B_, 128>>>(pred, feat);                 // launch 2
  dim3 g(NTILES, 2);
  gemm_k<<<g, 256>>>(fb);                              // launch 3 (profile target)
  merge_topk_k<<<B_, 256>>>();                         // launch 4
  kl_k<<<B_, 128>>>(sb);                               // launch 5
  final_k<<<1, 512>>>((float*)d_out);                  // launch 6
}

// round 5
// speedup vs baseline: 1.0663x; 1.0663x over previous
#include <cuda_runtime.h>
#include <cuda_bf16.h>
#include <stdint.h>
#include <math_constants.h>

#define B_  256
#define C_  345
#define D_  512
#define N_  50000
#define KN  5
#define BM  128
#define BN  128
#define BK  32
#define NTILES 391             /* ceil(50000 / 128) */

/* ---------------- device scratch (static allocation only) ---------------- */
__device__ __align__(16) float          g_p[B_ * C_];
__device__ float                        g_rowsq[B_];
__device__ __align__(16) float          g_fn[B_ * D_];
__device__ __align__(16) __nv_bfloat16  g_fnb[B_ * D_];
__device__ int                          g_owner[N_];
__device__ __align__(16) float          g_cv[(size_t)B_ * NTILES * 6];
__device__ __align__(16) int            g_ci[(size_t)B_ * NTILES * 6];
__device__ int                          g_idx[B_ * KN];
__device__ float                        g_lossparts[B_];

__device__ __forceinline__ int clampN(int n) {
  return (n < 0) ? 0 : ((n >= N_) ? (N_ - 1) : n);
}
__device__ __forceinline__ bool betterf(float v, int i, float v2, int i2) {
  return (v > v2) || (v == v2 && i < i2);
}
__device__ __forceinline__ void ins6(float v, int id, float* bv, int* bi) {
  if (betterf(v, id, bv[5], bi[5])) {
    bv[5] = v; bi[5] = id;
#pragma unroll
    for (int j = 5; j > 0; j--) {
      if (betterf(bv[j], bi[j], bv[j - 1], bi[j - 1])) {
        float tv = bv[j]; bv[j] = bv[j - 1]; bv[j - 1] = tv;
        int  ti = bi[j]; bi[j] = bi[j - 1]; bi[j - 1] = ti;
      }
    }
  }
}

/* ---------------- asm helpers (sm_80+ only: LDSM / LDGSTS / HMMA) ---------------- */
#define LDSM4(r, addr) \
  asm volatile("ldmatrix.sync.aligned.m8n8.x4.shared.b16 {%0,%1,%2,%3}, [%4];" \
    : "=r"((r)[0]), "=r"((r)[1]), "=r"((r)[2]), "=r"((r)[3]) : "r"(addr))

#define CPASYNC16(dst, src) \
  asm volatile("cp.async.cg.shared.global [%0], [%1], 16;" :: "r"(dst), "l"(src))
#define CPCOMMIT() asm volatile("cp.async.commit_group;")
#define CPWAIT0()  asm volatile("cp.async.wait_group 0;")

#define MMA16816(c, a, b0, b1) \
  asm volatile("mma.sync.aligned.m16n8k16.row.col.f32.bf16.bf16.f32 " \
    "{%0,%1,%2,%3}, {%4,%5,%6,%7}, {%8,%9}, {%0,%1,%2,%3};\n" \
    : "+f"((c)[0]), "+f"((c)[1]), "+f"((c)[2]), "+f"((c)[3]) \
    : "r"((a)[0]), "r"((a)[1]), "r"((a)[2]), "r"((a)[3]), "r"(b0), "r"(b1))

/* ---------------- prep: softmax | fnorm | owner-init ---------------- */
__global__ void prep_k(const float* __restrict__ pred, const float* __restrict__ feat) {
  int t = threadIdx.x;
  __shared__ float red[128];
  if (blockIdx.x < B_) {
    int b = blockIdx.x;
    const float* row = pred + (size_t)b * C_;
    float mx = -CUDART_INF_F;
    for (int c = t; c < C_; c += 128) mx = fmaxf(mx, row[c]);
    red[t] = mx; __syncthreads();
    for (int s = 64; s > 0; s >>= 1) { if (t < s) red[t] = fmaxf(red[t], red[t + s]); __syncthreads(); }
    mx = red[0]; __syncthreads();
    float sm = 0.f;
    for (int c = t; c < C_; c += 128) sm += expf(row[c] - mx);
    red[t] = sm; __syncthreads();
    for (int s = 64; s > 0; s >>= 1) { if (t < s) red[t] += red[t + s]; __syncthreads(); }
    float inv = 1.f / red[0]; __syncthreads();
    float sq = 0.f;
    for (int c = t; c < C_; c += 128) {
      float v = expf(row[c] - mx) * inv;
      g_p[(size_t)b * C_ + c] = v;
      sq += v * v;
    }
    red[t] = sq; __syncthreads();
    for (int s = 64; s > 0; s >>= 1) { if (t < s) red[t] += red[t + s]; __syncthreads(); }
    if (t == 0) g_rowsq[b] = red[0];
  } else if (blockIdx.x < 2 * B_) {
    int b = blockIdx.x - B_;
    const float* row = feat + (size_t)b * D_;
    float sq = 0.f;
    for (int c = t; c < D_; c += 128) { float v = row[c]; sq += v * v; }
    red[t] = sq; __syncthreads();
    for (int s = 64; s > 0; s >>= 1) { if (t < s) red[t] += red[t + s]; __syncthreads(); }
    float inv = 1.f / fmaxf(sqrtf(red[0]), 1e-12f);
    for (int c = t; c < D_; c += 128) {
      float v = row[c] * inv;
      g_fn[(size_t)b * D_ + c]  = v;
      g_fnb[(size_t)b * D_ + c] = __float2bfloat16(v);
    }
  } else {
    int i = (blockIdx.x - 2 * B_) * 128 + t;
    if (i < N_) g_owner[i] = -1;
  }
}

__global__ void scatter_owner_k(const int* __restrict__ trg) {
  int b = threadIdx.x;
  atomicMax(&g_owner[clampN(trg[b])], b);
}

/* ---- bf16 mma.sync GEMM (ldmatrix + cp.async) + fused per-tile top-6 ---- */
__global__ void __launch_bounds__(256, 2) gemm_k(const float* __restrict__ fb) {
  /* smem: [GEMM] sA[2][128][40]bf16 @0 (20480) + sB[2][128][40]bf16 @20480 (20480)
           [EPI ] scanTile 64x132 f32 @0 (33792) + mbV @33792 (6144) + mbI @39936 (6144) */
  __shared__ __align__(16) char smemRaw[46080];
  __shared__ const float* sPtr[128];

  const int tid  = threadIdx.x;
  const int lane = tid & 31;
  const int warp = tid >> 5;
  const int wm   = warp >> 2;      /* 0..1 : 64 rows  */
  const int wn   = warp & 3;       /* 0..3 : 32 cols  */
  const int mBase = blockIdx.y * BM;
  const int nBase = blockIdx.x * BN;

  const uint32_t smem0 = (uint32_t)__cvta_generic_to_shared(smemRaw);
  /* sA buf b @ smem0 + b*10240 ; sB buf b @ smem0 + 20480 + b*10240 */

  if (tid < 128) {
    int g = nBase + tid;
    if (g >= N_) g = N_ - 1;
    int ow = g_owner[g];
    sPtr[tid] = (ow >= 0) ? (g_fn + (size_t)ow * D_) : (fb + (size_t)g * D_);
  }
  __syncthreads();

  float acc[4][4][4];
#pragma unroll
  for (int i = 0; i < 4; i++)
#pragma unroll
    for (int j = 0; j < 4; j++)
#pragma unroll
      for (int k = 0; k < 4; k++) acc[i][j][k] = 0.f;

  /* ldmatrix base addresses (buffer 0; add buf*10240 + ks*32 at use) */
  uint32_t aAddr[4], bAddr[2];
  {
    int ar = wm * 64 + (lane & 15);
    int ac = (lane >> 4) * 16;                       /* bytes: k-half */
#pragma unroll
    for (int mi = 0; mi < 4; mi++) aAddr[mi] = smem0 + (ar + mi * 16) * 80 + ac;
    int bn = wn * 32 + (lane & 7) + ((lane >> 4) << 3);
    int bc = ((lane >> 3) & 1) * 16;
#pragma unroll
    for (int n2 = 0; n2 < 2; n2++) bAddr[n2] = smem0 + 20480 + (bn + n2 * 16) * 80 + bc;
  }

  /* A cp.async fixed indices: iter t covers m = (tid>>2) + t*64, kc = tid&3 */
  const int aM = tid >> 2, aK = tid & 3;
  /* B staging fixed indices: iter t: n = (tid + t*256)>>3, kc = (tid + t*256)&7 */

  float4 bS[4];

  /* ---- prologue: chunk 0 ---- */
#pragma unroll
  for (int t = 0; t < 2; t++)
    CPASYNC16(smem0 + (aM + t * 64) * 80 + aK * 16,
              g_fnb + (size_t)(mBase + aM + t * 64) * D_ + aK * 8);
  CPCOMMIT();
#pragma unroll
  for (int t = 0; t < 4; t++) {
    int idx = tid + t * 256, n = idx >> 3, kc = idx & 7;
    bS[t] = *(const float4*)(sPtr[n] + kc * 4);
  }
#pragma unroll
  for (int t = 0; t < 4; t++) {
    int idx = tid + t * 256, n = idx >> 3, kc = idx & 7;
    __nv_bfloat162 lo = __floats2bfloat162_rn(bS[t].x, bS[t].y);
    __nv_bfloat162 hi = __floats2bfloat162_rn(bS[t].z, bS[t].w);
    uint2 v; v.x = *(uint32_t*)&lo; v.y = *(uint32_t*)&hi;
    *(uint2*)(smemRaw + 20480 + n * 80 + kc * 8) = v;
  }
  CPWAIT0();
  __syncthreads();

#pragma unroll 1
  for (int ch = 0; ch < 16; ch++) {
    const int buf = ch & 1;
    const int nb  = buf ^ 1;
    if (ch + 1 < 16) {
      const int k0 = (ch + 1) * BK;
#pragma unroll
      for (int t = 0; t < 2; t++)
        CPASYNC16(smem0 + nb * 10240 + (aM + t * 64) * 80 + aK * 16,
                  g_fnb + (size_t)(mBase + aM + t * 64) * D_ + k0 + aK * 8);
      CPCOMMIT();
#pragma unroll
      for (int t = 0; t < 4; t++) {
        int idx = tid + t * 256, n = idx >> 3, kc = idx & 7;
        bS[t] = *(const float4*)(sPtr[n] + k0 + kc * 4);
      }
    }
    /* compute on buf: 2 k-steps of (4+2 LDSM.x4, 16 HMMA) */
#pragma unroll
    for (int ks = 0; ks < 2; ks++) {
      uint32_t a[4][4], b2[2][4];
      const uint32_t koff = buf * 10240 + ks * 32;
#pragma unroll
      for (int mi = 0; mi < 4; mi++) LDSM4(a[mi], aAddr[mi] + koff);
#pragma unroll
      for (int n2 = 0; n2 < 2; n2++) LDSM4(b2[n2], bAddr[n2] + koff);
#pragma unroll
      for (int mi = 0; mi < 4; mi++)
#pragma unroll
        for (int ni = 0; ni < 4; ni++)
          MMA16816(acc[mi][ni], a[mi], b2[ni >> 1][(ni & 1) * 2], b2[ni >> 1][(ni & 1) * 2 + 1]);
    }
    if (ch + 1 < 16) {
#pragma unroll
      for (int t = 0; t < 4; t++) {
        int idx = tid + t * 256, n = idx >> 3, kc = idx & 7;
        __nv_bfloat162 lo = __floats2bfloat162_rn(bS[t].x, bS[t].y);
        __nv_bfloat162 hi = __floats2bfloat162_rn(bS[t].z, bS[t].w);
        uint2 v; v.x = *(uint32_t*)&lo; v.y = *(uint32_t*)&hi;
        *(uint2*)(smemRaw + 20480 + nb * 10240 + n * 80 + kc * 8) = v;
      }
      CPWAIT0();
      __syncthreads();
    }
  }

  /* ---- fused epilogue: per-row top-6 of this 128-col tile, two 64-row halves ---- */
  float* scanTile = (float*)smemRaw;            /* [64][132] */
  float* mbV = (float*)(smemRaw + 33792);       /* [64][4][6] */
  int*   mbI = (int*)(smemRaw + 39936);         /* [64][4][6] */

#pragma unroll 1
  for (int half = 0; half < 2; half++) {
    __syncthreads();
    if (wm == half) {
#pragma unroll
      for (int mi = 0; mi < 4; mi++) {
        int lr = mi * 16 + (lane >> 2);
#pragma unroll
        for (int ni = 0; ni < 4; ni++) {
          int c = wn * 32 + ni * 8 + (lane & 3) * 2;
          *(float2*)&scanTile[lr * 132 + c]       = make_float2(acc[mi][ni][0], acc[mi][ni][1]);
          *(float2*)&scanTile[(lr + 8) * 132 + c] = make_float2(acc[mi][ni][2], acc[mi][ni][3]);
        }
      }
    }
    __syncthreads();
    {
      int lr  = tid >> 2;
      int seg = tid & 3;
      int cs  = seg * 32;
      float bv[6]; int bi[6];
#pragma unroll
      for (int j = 0; j < 6; j++) { bv[j] = -CUDART_INF_F; bi[j] = 0x7fffffff; }
#pragma unroll 4
      for (int i = 0; i < 32; i++) {
        int gcol = nBase + cs + i;
        float v = scanTile[lr * 132 + cs + i];
        if (gcol < N_) ins6(v, gcol, bv, bi);
      }
#pragma unroll
      for (int j = 0; j < 6; j++) {
        mbV[(lr * 4 + seg) * 6 + j] = bv[j];
        mbI[(lr * 4 + seg) * 6 + j] = bi[j];
      }
    }
    __syncthreads();
    if ((tid & 3) == 0) {
      int lr = tid >> 2;
      float bv[6]; int bi[6];
#pragma unroll
      for (int j = 0; j < 6; j++) { bv[j] = -CUDART_INF_F; bi[j] = 0x7fffffff; }
#pragma unroll
      for (int s = 0; s < 4; s++)
#pragma unroll
        for (int j = 0; j < 6; j++)
          ins6(mbV[(lr * 4 + s) * 6 + j], mbI[(lr * 4 + s) * 6 + j], bv, bi);
      int grow = mBase + half * 64 + lr;
      size_t base = ((size_t)grow * NTILES + blockIdx.x) * 6;
#pragma unroll
      for (int j = 0; j < 6; j++) { g_cv[base + j] = bv[j]; g_ci[base + j] = bi[j]; }
    }
  }
}

/* ---------------- merge per-tile candidates -> global top-6, drop rank-0 -------------- */
__global__ void merge_topk_k() {
  const int b = blockIdx.x, t = threadIdx.x;
  __shared__ float sv[256 * 6];
  __shared__ int   si[256 * 6];

  float bv[6]; int bi[6];
#pragma unroll
  for (int j = 0; j < 6; j++) { bv[j] = -CUDART_INF_F; bi[j] = 0x7fffffff; }

  const float* cv = g_cv + (size_t)b * NTILES * 6;
  const int*   ci = g_ci + (size_t)b * NTILES * 6;
  for (int e = t; e < NTILES * 6; e += 256)
    ins6(cv[e], ci[e], bv, bi);

#pragma unroll
  for (int j = 0; j < 6; j++) { sv[t * 6 + j] = bv[j]; si[t * 6 + j] = bi[j]; }
  __syncthreads();

  if (t < 32) {
    float mv[6]; int mi_[6];
#pragma unroll
    for (int j = 0; j < 6; j++) { mv[j] = -CUDART_INF_F; mi_[j] = 0x7fffffff; }
    for (int src = t; src < 256; src += 32)
      for (int j = 0; j < 6; j++)
        ins6(sv[src * 6 + j], si[src * 6 + j], mv, mi_);
#pragma unroll
    for (int j = 0; j < 6; j++) { sv[t * 6 + j] = mv[j]; si[t * 6 + j] = mi_[j]; }
  }
  __syncthreads();

  if (t == 0) {
    float mv[6]; int mi_[6];
#pragma unroll
    for (int j = 0; j < 6; j++) { mv[j] = -CUDART_INF_F; mi_[j] = 0x7fffffff; }
    for (int src = 0; src < 32; src++)
      for (int j = 0; j < 6; j++)
        ins6(sv[src * 6 + j], si[src * 6 + j], mv, mi_);
#pragma unroll
    for (int j = 1; j < 6; j++) g_idx[b * KN + (j - 1)] = mi_[j];
  }
}

/* ---------------- KL term per batch row ---------------- */
__global__ void kl_k(const float* __restrict__ sb) {
  const int b = blockIdx.x, t = threadIdx.x;
  __shared__ float red[128];
  float acc = 0.f;
  for (int k = 0; k < KN; k++) {
    int n  = g_idx[b * KN + k];
    int ow = g_owner[n];
    const float* srow = (ow >= 0) ? (g_p + (size_t)ow * C_)
                                  : (sb + (size_t)n * C_);
    for (int c = t; c < C_; c += 128) {
      float s = srow[c];
      acc += s * (logf(s) - g_p[(size_t)b * C_ + c]);
    }
  }
  red[t] = acc; __syncthreads();
  for (int s = 64; s > 0; s >>= 1) { if (t < s) red[t] += red[t + s]; __syncthreads(); }
  if (t == 0) g_lossparts[b] = red[0];
}

/* ---------------- final: loss = mean(kl) + (||q||^2 - sum rowsq)/B ---------------- */
__global__ void final_k(float* __restrict__ out) {
  __shared__ float r1[512], r2[512], r3[512];
  int t = threadIdx.x;
  float a = 0.f, q2 = 0.f, rr = 0.f;
  if (t < B_) { a = g_lossparts[t]; rr = g_rowsq[t]; }
  for (int c = t; c < C_; c += 512) {
    float s = 0.f;
    for (int b = 0; b < B_; b++) s += g_p[(size_t)b * C_ + c];
    q2 += s * s;
  }
  r1[t] = a; r2[t] = q2; r3[t] = rr; __syncthreads();
  for (int s = 256; s > 0; s >>= 1) {
    if (t < s) { r1[t] += r1[t + s]; r2[t] += r2[t + s]; r3[t] += r3[t + s]; }
    __syncthreads();
  }
  if (t == 0) out[0] = r1[0] / (float)B_ + 1.0f * ((r2[0] - r3[0]) / (float)B_);
}

/* ---------------- launch ---------------- */
extern "C" void kernel_launch(void* const* d_in, const int* in_sizes, int n_in,
                              void* d_out, int out_size) {
  (void)in_sizes; (void)n_in; (void)out_size;
  const float* feat = (const float*)d_in[0];
  const float* pred = (const float*)d_in[1];
  const float* fb   = (const float*)d_in[2];
  const float* sb   = (const float*)d_in[3];
  const int*   trg  = (const int*)d_in[4];

  prep_k<<<2 * B_ + (N_ + 127) / 128, 128>>>(pred, feat);  // softmax|fnorm|owner-init
  scatter_owner_k<<<1, B_>>>(trg);
  dim3 g(NTILES, 2);
  gemm_k<<<g, 256>>>(fb);                                  // launch 2 (profile target)
  merge_topk_k<<<B_, 256>>>();
  kl_k<<<B_, 128>>>(sb);
  final_k<<<1, 512>>>((float*)d_out);
}